// round 2
// baseline (speedup 1.0000x reference)
#include <cuda_runtime.h>

// LoRA fused linear: out[M,N] = x[M,K] @ W[N,K]^T + b[N] + 2 * (x @ A[16,K]^T) @ B[N,16]^T
// M=8192, N=4096, K=4096, R=16 (fp32 everywhere; exact math for rel_err ~1e-6)

#define SCALING 2.0f
#define R_RANK 16

// scratch for xa = x @ A^T  (allocation-free rule: __device__ global)
__device__ float g_xa[8192 * R_RANK];

// ---------------------------------------------------------------------------
// Kernel A: xa[m][r] = sum_k x[m][k] * A[r][k]
// 256 threads = 8 warps, each warp owns 4 rows; A staged in 32KB shared chunks.
// ---------------------------------------------------------------------------
__global__ __launch_bounds__(256)
void xa_kernel(const float* __restrict__ x, const float* __restrict__ A,
               int M, int K) {
    const int CHUNK = 512;
    __shared__ float As[R_RANK][CHUNK];   // 32 KB

    int lane = threadIdx.x & 31;
    int warp = threadIdx.x >> 5;
    int row0 = blockIdx.x * 32 + warp * 4;

    float acc[4][R_RANK];
#pragma unroll
    for (int a = 0; a < 4; a++)
#pragma unroll
        for (int r = 0; r < R_RANK; r++) acc[a][r] = 0.f;

    for (int c = 0; c < K; c += CHUNK) {
        __syncthreads();
        // cooperative load of A chunk: 16 x 512 floats = 2048 float4
        for (int f = threadIdx.x; f < R_RANK * (CHUNK / 4); f += blockDim.x) {
            int r  = f / (CHUNK / 4);
            int k4 = f % (CHUNK / 4);
            *(float4*)&As[r][k4 * 4] =
                *(const float4*)&A[(size_t)r * K + c + k4 * 4];
        }
        __syncthreads();
#pragma unroll
        for (int it = 0; it < CHUNK / 128; ++it) {
            int kk = it * 128 + lane * 4;
            float4 xv[4];
#pragma unroll
            for (int a = 0; a < 4; a++)
                xv[a] = *(const float4*)&x[(size_t)(row0 + a) * K + c + kk];
#pragma unroll
            for (int r = 0; r < R_RANK; r++) {
                float4 av = *(const float4*)&As[r][kk];
#pragma unroll
                for (int a = 0; a < 4; a++)
                    acc[a][r] += xv[a].x * av.x + xv[a].y * av.y
                               + xv[a].z * av.z + xv[a].w * av.w;
            }
        }
    }

    // warp reduction, lane 0 writes
#pragma unroll
    for (int a = 0; a < 4; a++)
#pragma unroll
        for (int r = 0; r < R_RANK; r++) {
            float v = acc[a][r];
#pragma unroll
            for (int o = 16; o > 0; o >>= 1)
                v += __shfl_xor_sync(0xffffffffu, v, o);
            if (lane == 0) g_xa[(size_t)(row0 + a) * R_RANK + r] = v;
        }
}

// ---------------------------------------------------------------------------
// Kernel B: main fused GEMM. 128x128 block tile, BK=16, 256 threads, 8x8
// microtile, double-buffered transposed shared tiles, register-staged
// prefetch (one __syncthreads per k-tile). Epilogue fuses bias + 2*xa@B^T.
// ---------------------------------------------------------------------------
#define BM 128
#define BN 128
#define BK 16

__global__ __launch_bounds__(256, 2)
void lora_gemm_kernel(const float* __restrict__ x, const float* __restrict__ W,
                      const float* __restrict__ bias,
                      const float* __restrict__ loraB,
                      float* __restrict__ out,
                      int M, int N, int K) {
    __shared__ float Xs[2][BK][BM + 4];
    __shared__ float Ws[2][BK][BN + 4];

    const int tid = threadIdx.x;
    const int tx = tid & 15;        // 0..15 (cols)
    const int ty = tid >> 4;        // 0..15 (rows)
    const int bm = blockIdx.y * BM;
    const int bn = blockIdx.x * BN;

    // loader mapping: each thread loads 2 float4 from X and 2 from W per tile
    const int lrow = tid >> 2;              // 0..63
    const int lk   = (tid & 3) * 4;         // 0,4,8,12

    const float* xg = x + (size_t)(bm + lrow) * K + lk;
    const float* wg = W + (size_t)(bn + lrow) * K + lk;
    const size_t rstep = (size_t)64 * K;

    float acc[8][8];
#pragma unroll
    for (int i = 0; i < 8; i++)
#pragma unroll
        for (int j = 0; j < 8; j++) acc[i][j] = 0.f;

    float4 px0, px1, pw0, pw1;

    // prologue: load tile 0
    px0 = *(const float4*)(xg);
    px1 = *(const float4*)(xg + rstep);
    pw0 = *(const float4*)(wg);
    pw1 = *(const float4*)(wg + rstep);

#define STORE_TILE(buf)                                                        \
    do {                                                                       \
        Xs[buf][lk + 0][lrow] = px0.x; Xs[buf][lk + 1][lrow] = px0.y;          \
        Xs[buf][lk + 2][lrow] = px0.z; Xs[buf][lk + 3][lrow] = px0.w;          \
        Xs[buf][lk + 0][lrow + 64] = px1.x; Xs[buf][lk + 1][lrow + 64] = px1.y;\
        Xs[buf][lk + 2][lrow + 64] = px1.z; Xs[buf][lk + 3][lrow + 64] = px1.w;\
        Ws[buf][lk + 0][lrow] = pw0.x; Ws[buf][lk + 1][lrow] = pw0.y;          \
        Ws[buf][lk + 2][lrow] = pw0.z; Ws[buf][lk + 3][lrow] = pw0.w;          \
        Ws[buf][lk + 0][lrow + 64] = pw1.x; Ws[buf][lk + 1][lrow + 64] = pw1.y;\
        Ws[buf][lk + 2][lrow + 64] = pw1.z; Ws[buf][lk + 3][lrow + 64] = pw1.w;\
    } while (0)

    STORE_TILE(0);
    __syncthreads();

    const int NT = K / BK;
    for (int kt = 0; kt < NT; ++kt) {
        const int cur = kt & 1;
        const bool has_next = (kt + 1 < NT);
        if (has_next) {
            const float* xg2 = xg + (size_t)(kt + 1) * BK;
            const float* wg2 = wg + (size_t)(kt + 1) * BK;
            px0 = *(const float4*)(xg2);
            px1 = *(const float4*)(xg2 + rstep);
            pw0 = *(const float4*)(wg2);
            pw1 = *(const float4*)(wg2 + rstep);
        }
#pragma unroll
        for (int k = 0; k < BK; ++k) {
            float4 a0 = *(const float4*)&Xs[cur][k][ty * 4];
            float4 a1 = *(const float4*)&Xs[cur][k][ty * 4 + 64];
            float4 b0 = *(const float4*)&Ws[cur][k][tx * 4];
            float4 b1 = *(const float4*)&Ws[cur][k][tx * 4 + 64];
            float ar[8] = {a0.x, a0.y, a0.z, a0.w, a1.x, a1.y, a1.z, a1.w};
            float br[8] = {b0.x, b0.y, b0.z, b0.w, b1.x, b1.y, b1.z, b1.w};
#pragma unroll
            for (int i = 0; i < 8; i++)
#pragma unroll
                for (int j = 0; j < 8; j++)
                    acc[i][j] += ar[i] * br[j];
        }
        if (has_next) {
            STORE_TILE(cur ^ 1);
            __syncthreads();
        }
    }

    // ---------------- epilogue: + bias + 2 * xa @ B^T ----------------
    __syncthreads();
    float* sxa = &Xs[0][0][0];   // 128 x 16 xa tile   (2048 floats, fits)
    float* sbb = &Ws[0][0][0];   // 128 x 16 loraB tile
    for (int f = tid; f < 512; f += 256) {           // 512 float4 total
        int r  = f >> 2;
        int c4 = (f & 3) * 4;
        *(float4*)&sxa[r * R_RANK + c4] =
            *(const float4*)&g_xa[(size_t)(bm + r) * R_RANK + c4];
        *(float4*)&sbb[r * R_RANK + c4] =
            *(const float4*)&loraB[(size_t)(bn + r) * R_RANK + c4];
    }
    __syncthreads();

#pragma unroll
    for (int i = 0; i < 8; i++) {
        const int mloc = (i < 4) ? (ty * 4 + i) : (64 + ty * 4 + (i - 4));
        const int m = bm + mloc;
        float xar[R_RANK];
#pragma unroll
        for (int r = 0; r < R_RANK; r++) xar[r] = sxa[mloc * R_RANK + r];
#pragma unroll
        for (int jh = 0; jh < 2; jh++) {
            float4 o;
            float* op = &o.x;
#pragma unroll
            for (int jj = 0; jj < 4; jj++) {
                const int nloc = jh * 64 + tx * 4 + jj;
                float s = 0.f;
#pragma unroll
                for (int r = 0; r < R_RANK; r++)
                    s += xar[r] * sbb[nloc * R_RANK + r];
                const int j = jh * 4 + jj;
                op[jj] = acc[i][j] + bias[bn + nloc] + SCALING * s;
            }
            *(float4*)&out[(size_t)m * N + bn + jh * 64 + tx * 4] = o;
        }
    }
}

// ---------------------------------------------------------------------------
extern "C" void kernel_launch(void* const* d_in, const int* in_sizes, int n_in,
                              void* d_out, int out_size) {
    const float* x  = (const float*)d_in[0];  // [B,S,K] -> [M,K]
    const float* W  = (const float*)d_in[1];  // [N,K]
    const float* b  = (const float*)d_in[2];  // [N]
    const float* lA = (const float*)d_in[3];  // [R,K]
    const float* lB = (const float*)d_in[4];  // [N,R]
    float* out = (float*)d_out;

    const int N = in_sizes[2];
    const int K = in_sizes[1] / N;
    const int M = in_sizes[0] / K;

    // Kernel A: xa = x @ A^T  (32 rows per block)
    xa_kernel<<<M / 32, 256>>>(x, lA, M, K);

    // Kernel B: fused GEMM + bias + LoRA
    dim3 grid(N / BN, M / BM);
    lora_gemm_kernel<<<grid, 256>>>(x, W, b, lB, out, M, N, K);
}